// round 4
// baseline (speedup 1.0000x reference)
#include <cuda_runtime.h>

// Fuzzyfier: out[b,v,s,p] = mv if mv >= 0.1 else 0
//   mv = exp(-(x-c)^2 / (2 sigma^2)) = exp2((x-c)^2 * negk),
//   negk = -log2(e)/(2 sigma^2)  (precomputed per (v,p) in shared)
// Shapes: x (64,8,1024) f32, fuzzy_sets (8,64,2) f32, out (64,8,1024,64) f32.
// Round 4: STG.256 (st.global.v8.f32, sm_100a) — each lane writes 32B, one
// warp covers a full 8 x 128B span; halves store count + address ALU.

#define SEQ   1024
#define NP    64
#define NV    8
#define ALPHA 0.1f
#define ITERS 4            // v8 stores per thread
#define S_PER_BLOCK 128    // 32 s-lanes * 4 iters

__device__ __forceinline__ float ex2_approx(float a) {
    float r;
    asm("ex2.approx.f32 %0, %1;" : "=f"(r) : "f"(a));
    return r;
}

__device__ __forceinline__ void stg256_cs(float* p, const float* r) {
    asm volatile(
        "st.global.cs.v8.f32 [%0], {%1,%2,%3,%4,%5,%6,%7,%8};"
        :: "l"(p),
           "f"(r[0]), "f"(r[1]), "f"(r[2]), "f"(r[3]),
           "f"(r[4]), "f"(r[5]), "f"(r[6]), "f"(r[7])
        : "memory");
}

__global__ __launch_bounds__(256, 4)
void fuzzyfier_kernel(const float* __restrict__ x,
                      const float* __restrict__ fs,
                      float* __restrict__ out)
{
    __shared__ float s_c[NP];   // centers for this v
    __shared__ float s_k[NP];   // -log2(e)/(2*sigma^2) for this v

    const int tid = threadIdx.x;
    const int bv  = blockIdx.y;          // b*NV + v
    const int v   = bv & (NV - 1);

    if (tid < NP) {
        float c  = fs[(v * NP + tid) * 2 + 0];
        float sg = fs[(v * NP + tid) * 2 + 1];
        s_c[tid] = c;
        s_k[tid] = -1.4426950408889634f / (2.0f * sg * sg);
    }
    __syncthreads();

    const int p8 = tid & 7;     // which 8-float chunk within the 64-wide P row
    const int sl = tid >> 3;    // 0..31: s-lane within the block tile

    // Load this thread's 8 centers / 8 coefficients from shared.
    float c[8], k[8];
    #pragma unroll
    for (int j = 0; j < 8; j++) {
        c[j] = s_c[p8 * 8 + j];
        k[j] = s_k[p8 * 8 + j];
    }

    const int s0 = blockIdx.x * S_PER_BLOCK + sl;   // first s this thread owns
    const float* xp = x + bv * SEQ + s0;

    // Prefetch the 4 x values (independent broadcast LDGs).
    float xv[ITERS];
    #pragma unroll
    for (int i = 0; i < ITERS; i++)
        xv[i] = __ldg(&xp[i * 32]);

    // Store base: out[(bv*SEQ + s0)*64 + p8*8]; iter stride = 32 s-rows * 64.
    float* op = out + (size_t)(bv * SEQ + s0) * 64 + p8 * 8;

    #pragma unroll
    for (int i = 0; i < ITERS; i++) {
        float r[8];
        #pragma unroll
        for (int j = 0; j < 8; j++) {
            float d = xv[i] - c[j];
            float m = ex2_approx(d * d * k[j]);
            r[j] = (m >= ALPHA) ? m : 0.0f;
        }
        stg256_cs(op + i * (32 * 64), r);
    }
}

extern "C" void kernel_launch(void* const* d_in, const int* in_sizes, int n_in,
                              void* d_out, int out_size)
{
    const float* x  = (const float*)d_in[0];          // (64,8,1024)
    const float* fs = (const float*)d_in[1];          // (8,64,2)
    float* out      = (float*)d_out;                  // (64,8,1024,64)

    const int BV = in_sizes[0] / SEQ;                 // 512

    dim3 grid(SEQ / S_PER_BLOCK, BV);
    fuzzyfier_kernel<<<grid, 256>>>(x, fs, out);
}

// round 5
// speedup vs baseline: 1.1538x; 1.1538x over previous
#include <cuda_runtime.h>
#include <cstdint>

// Fuzzyfier: out[b,v,s,p] = mv if mv >= 0.1 else 0
//   mv = exp2((x-c)^2 * negk), negk = -log2(e)/(2 sigma^2)
// Shapes: x (64,8,1024) f32, fuzzy_sets (8,64,2) f32, out (64,8,1024,64) f32.
//
// Round 5: compute into SMEM, drain with 1D TMA bulk stores
// (cp.async.bulk.global.shared::cta). Each block owns one (bv, 128-row s-tile)
// = a contiguous 32KB output span, issued as two async 16KB bulk stores.
// Removes STG latency/LSU-queue exposure from the warp critical path.

#define SEQ   1024
#define NP    64
#define NV    8
#define ALPHA 0.1f
#define SUB_S 64            // s-rows per sub-tile (16KB)
#define NSUB  2             // sub-tiles per block (128 s-rows total)
#define S_PER_BLOCK (SUB_S * NSUB)

__device__ __forceinline__ float ex2_approx(float a) {
    float r;
    asm("ex2.approx.f32 %0, %1;" : "=f"(r) : "f"(a));
    return r;
}

__device__ __forceinline__ uint32_t smem_u32(const void* p) {
    uint32_t a;
    asm("{ .reg .u64 t; cvta.to.shared.u64 t, %1; cvt.u32.u64 %0, t; }"
        : "=r"(a) : "l"(p));
    return a;
}

__global__ __launch_bounds__(256)
void fuzzyfier_kernel(const float* __restrict__ x,
                      const float* __restrict__ fs,
                      float* __restrict__ out)
{
    __shared__ float  s_c[NP];                    // centers for this v
    __shared__ float  s_k[NP];                    // -log2(e)/(2 sigma^2)
    __shared__ __align__(16) float4 buf[NSUB][SUB_S * 16];  // 2 x 16KB tiles

    const int tid = threadIdx.x;
    const int bv  = blockIdx.y;          // b*NV + v
    const int v   = bv & (NV - 1);

    if (tid < NP) {
        float c  = fs[(v * NP + tid) * 2 + 0];
        float sg = fs[(v * NP + tid) * 2 + 1];
        s_c[tid] = c;
        s_k[tid] = -1.4426950408889634f / (2.0f * sg * sg);
    }
    __syncthreads();

    const int p4 = tid & 15;    // float4 index within 64-wide P row
    const int sl = tid >> 4;    // 0..15: s-lane

    const float4 c = reinterpret_cast<const float4*>(s_c)[p4];
    const float4 k = reinterpret_cast<const float4*>(s_k)[p4];

    const int s_tile = blockIdx.x * S_PER_BLOCK;

    #pragma unroll
    for (int sub = 0; sub < NSUB; sub++) {
        const int s_base = s_tile + sub * SUB_S;
        const float* xp = x + bv * SEQ + s_base + sl;

        // Prefetch the 4 x values this thread needs (broadcast LDGs).
        float xv[4];
        #pragma unroll
        for (int i = 0; i < 4; i++)
            xv[i] = __ldg(&xp[i * 16]);

        // Compute 4 float4 results into the staging buffer (conflict-free:
        // consecutive lanes hit consecutive 16B banks).
        #pragma unroll
        for (int i = 0; i < 4; i++) {
            const int srow = i * 16 + sl;
            float d;
            float4 r;
            d = xv[i] - c.x; r.x = ex2_approx(d * d * k.x);
            d = xv[i] - c.y; r.y = ex2_approx(d * d * k.y);
            d = xv[i] - c.z; r.z = ex2_approx(d * d * k.z);
            d = xv[i] - c.w; r.w = ex2_approx(d * d * k.w);
            r.x = (r.x >= ALPHA) ? r.x : 0.0f;
            r.y = (r.y >= ALPHA) ? r.y : 0.0f;
            r.z = (r.z >= ALPHA) ? r.z : 0.0f;
            r.w = (r.w >= ALPHA) ? r.w : 0.0f;
            buf[sub][srow * 16 + p4] = r;
        }

        // Make generic-proxy smem writes visible to the async proxy, then
        // hand the whole 16KB tile to the TMA engine from one thread.
        asm volatile("fence.proxy.async.shared::cta;" ::: "memory");
        __syncthreads();

        if (tid == 0) {
            float* gdst = out + (size_t)(bv * SEQ + s_base) * 64;
            const uint32_t saddr = smem_u32(&buf[sub][0]);
            asm volatile(
                "cp.async.bulk.global.shared::cta.bulk_group [%0], [%1], %2;"
                :: "l"(gdst), "r"(saddr), "n"(SUB_S * 64 * 4)
                : "memory");
            asm volatile("cp.async.bulk.commit_group;" ::: "memory");
        }
    }

    // Block may not exit while TMA still reads its smem.
    if (tid == 0)
        asm volatile("cp.async.bulk.wait_group.read 0;" ::: "memory");
}

extern "C" void kernel_launch(void* const* d_in, const int* in_sizes, int n_in,
                              void* d_out, int out_size)
{
    const float* x  = (const float*)d_in[0];          // (64,8,1024)
    const float* fs = (const float*)d_in[1];          // (8,64,2)
    float* out      = (float*)d_out;                  // (64,8,1024,64)

    const int BV = in_sizes[0] / SEQ;                 // 512

    dim3 grid(SEQ / S_PER_BLOCK, BV);                 // (8, 512)
    fuzzyfier_kernel<<<grid, 256>>>(x, fs, out);
}

// round 6
// speedup vs baseline: 1.2516x; 1.0847x over previous
#include <cuda_runtime.h>
#include <cstdint>

// Fuzzyfier: out[b,v,s,p] = mv if mv >= 0.1 else 0
//   mv = exp2((x-c)^2 * negk), negk = -log2(e)/(2 sigma^2)
// Shapes: x (64,8,1024) f32, fuzzy_sets (8,64,2) f32, out (64,8,1024,64) f32.
//
// Round 6: R5's SMEM-staged TMA bulk stores + L2::cache_hint evict_first.
// R5 showed TMA wins in-kernel (22.98us isolated) but default L2 policy
// poisons steady-state replays (dirty-L2 writeback stall). evict_first on the
// bulk store = the .cs semantics that made R3 fast in steady state.

#define SEQ   1024
#define NP    64
#define NV    8
#define ALPHA 0.1f
#define SUB_S 64            // s-rows per sub-tile (16KB)
#define NSUB  2             // sub-tiles per block (128 s-rows total)
#define S_PER_BLOCK (SUB_S * NSUB)

__device__ __forceinline__ float ex2_approx(float a) {
    float r;
    asm("ex2.approx.f32 %0, %1;" : "=f"(r) : "f"(a));
    return r;
}

__device__ __forceinline__ uint32_t smem_u32(const void* p) {
    uint32_t a;
    asm("{ .reg .u64 t; cvta.to.shared.u64 t, %1; cvt.u32.u64 %0, t; }"
        : "=r"(a) : "l"(p));
    return a;
}

__global__ __launch_bounds__(256)
void fuzzyfier_kernel(const float* __restrict__ x,
                      const float* __restrict__ fs,
                      float* __restrict__ out)
{
    __shared__ float  s_c[NP];                    // centers for this v
    __shared__ float  s_k[NP];                    // -log2(e)/(2 sigma^2)
    __shared__ __align__(16) float4 buf[NSUB][SUB_S * 16];  // 2 x 16KB tiles

    const int tid = threadIdx.x;
    const int bv  = blockIdx.y;          // b*NV + v
    const int v   = bv & (NV - 1);

    if (tid < NP) {
        float c  = fs[(v * NP + tid) * 2 + 0];
        float sg = fs[(v * NP + tid) * 2 + 1];
        s_c[tid] = c;
        s_k[tid] = -1.4426950408889634f / (2.0f * sg * sg);
    }
    __syncthreads();

    const int p4 = tid & 15;    // float4 index within 64-wide P row
    const int sl = tid >> 4;    // 0..15: s-lane

    const float4 c = reinterpret_cast<const float4*>(s_c)[p4];
    const float4 k = reinterpret_cast<const float4*>(s_k)[p4];

    const int s_tile = blockIdx.x * S_PER_BLOCK;

    // Streaming (evict-first) L2 policy for the write-once output.
    uint64_t pol;
    asm("createpolicy.fractional.L2::evict_first.b64 %0, 1.0;" : "=l"(pol));

    #pragma unroll
    for (int sub = 0; sub < NSUB; sub++) {
        const int s_base = s_tile + sub * SUB_S;
        const float* xp = x + bv * SEQ + s_base + sl;

        // Prefetch the 4 x values this thread needs (broadcast LDGs).
        float xv[4];
        #pragma unroll
        for (int i = 0; i < 4; i++)
            xv[i] = __ldg(&xp[i * 16]);

        // Compute 4 float4 results into the staging buffer (conflict-free:
        // consecutive lanes hit consecutive 16B banks).
        #pragma unroll
        for (int i = 0; i < 4; i++) {
            const int srow = i * 16 + sl;
            float d;
            float4 r;
            d = xv[i] - c.x; r.x = ex2_approx(d * d * k.x);
            d = xv[i] - c.y; r.y = ex2_approx(d * d * k.y);
            d = xv[i] - c.z; r.z = ex2_approx(d * d * k.z);
            d = xv[i] - c.w; r.w = ex2_approx(d * d * k.w);
            r.x = (r.x >= ALPHA) ? r.x : 0.0f;
            r.y = (r.y >= ALPHA) ? r.y : 0.0f;
            r.z = (r.z >= ALPHA) ? r.z : 0.0f;
            r.w = (r.w >= ALPHA) ? r.w : 0.0f;
            buf[sub][srow * 16 + p4] = r;
        }

        // Make generic-proxy smem writes visible to the async proxy, then
        // hand the 16KB tile to the TMA engine from one thread.
        asm volatile("fence.proxy.async.shared::cta;" ::: "memory");
        __syncthreads();

        if (tid == 0) {
            float* gdst = out + (size_t)(bv * SEQ + s_base) * 64;
            const uint32_t saddr = smem_u32(&buf[sub][0]);
            asm volatile(
                "cp.async.bulk.global.shared::cta.bulk_group.L2::cache_hint"
                " [%0], [%1], %2, %3;"
                :: "l"(gdst), "r"(saddr), "n"(SUB_S * 64 * 4), "l"(pol)
                : "memory");
            asm volatile("cp.async.bulk.commit_group;" ::: "memory");
        }
    }

    // Block may not exit while TMA still reads its smem.
    if (tid == 0)
        asm volatile("cp.async.bulk.wait_group.read 0;" ::: "memory");
}

extern "C" void kernel_launch(void* const* d_in, const int* in_sizes, int n_in,
                              void* d_out, int out_size)
{
    const float* x  = (const float*)d_in[0];          // (64,8,1024)
    const float* fs = (const float*)d_in[1];          // (8,64,2)
    float* out      = (float*)d_out;                  // (64,8,1024,64)

    const int BV = in_sizes[0] / SEQ;                 // 512

    dim3 grid(SEQ / S_PER_BLOCK, BV);                 // (8, 512)
    fuzzyfier_kernel<<<grid, 256>>>(x, fs, out);
}